// round 12
// baseline (speedup 1.0000x reference)
#include <cuda_runtime.h>
#include <cuda_fp16.h>
#include <math.h>
#include <math_constants.h>
#include <cstdint>

#define BATCH  4
#define SEQ    2048
#define DMODEL 1024
#define NHEADS 16
#define DHEAD  64

// Scratch (device globals — allocation-free per harness rules)
__device__ __half g_qh[(size_t)BATCH * NHEADS * SEQ * DHEAD];   // [b,h,s,d] scaled
__device__ __half g_kh[(size_t)BATCH * NHEADS * SEQ * DHEAD];   // [b,h,s,d]
__device__ __half g_vt[(size_t)BATCH * NHEADS * DHEAD * SEQ];   // [b,h,d,s]
__device__ __half g_attnh[(size_t)BATCH * SEQ * DMODEL];        // [b,s,dm]
__device__ __half g_xh[(size_t)BATCH * SEQ * DMODEL];
__device__ __half g_w1h[(size_t)3 * DMODEL * DMODEL];
__device__ __half g_w2h[(size_t)DMODEL * DMODEL];

// ---------------------------------------------------------------------------
// helpers
// ---------------------------------------------------------------------------
__device__ __forceinline__ uint32_t smem_u32(const void* p) {
    uint32_t a;
    asm("{ .reg .u64 t; cvta.to.shared.u64 t, %1; cvt.u32.u64 %0, t; }"
        : "=r"(a) : "l"(p));
    return a;
}

__device__ __forceinline__ void cp16(uint32_t dst, const void* src) {
    asm volatile("cp.async.cg.shared.global [%0], [%1], 16;"
                 :: "r"(dst), "l"(src));
}

#define CP_COMMIT()  asm volatile("cp.async.commit_group;" ::: "memory")
#define CP_WAIT(n)   asm volatile("cp.async.wait_group %0;" :: "n"(n) : "memory")

__device__ __forceinline__ uint32_t lds32(const __half* p) {
    return *(const uint32_t*)p;
}

// D = A(16x16 f16, row) * B(16x8 f16, col) + D   (f32 accum)
__device__ __forceinline__ void mma_f16(float c[4],
                                        uint32_t a0, uint32_t a1,
                                        uint32_t a2, uint32_t a3,
                                        uint32_t b0, uint32_t b1) {
    asm volatile(
        "mma.sync.aligned.m16n8k16.row.col.f32.f16.f16.f32 "
        "{%0,%1,%2,%3}, {%4,%5,%6,%7}, {%8,%9}, {%0,%1,%2,%3};"
        : "+f"(c[0]), "+f"(c[1]), "+f"(c[2]), "+f"(c[3])
        : "r"(a0), "r"(a1), "r"(a2), "r"(a3), "r"(b0), "r"(b1));
}

// ---------------------------------------------------------------------------
// one-time fp32 -> fp16 conversion (8 floats / thread)
// ---------------------------------------------------------------------------
__global__ __launch_bounds__(256) void to_f16_k(
    const float* __restrict__ s, __half* __restrict__ d, int ngrp)
{
    int i = blockIdx.x * blockDim.x + threadIdx.x;
    if (i < ngrp) {
        float4 v0 = *(const float4*)(s + (size_t)i * 8);
        float4 v1 = *(const float4*)(s + (size_t)i * 8 + 4);
        __half2* o = (__half2*)(d + (size_t)i * 8);
        o[0] = __floats2half2_rn(v0.x, v0.y);
        o[1] = __floats2half2_rn(v0.z, v0.w);
        o[2] = __floats2half2_rn(v1.x, v1.y);
        o[3] = __floats2half2_rn(v1.z, v1.w);
    }
}

// ===========================================================================
// FP16 mma.sync GEMM (NT): C[m,n] = sum_k A[m,k] * W[n,k] + bias[n]
// 128x128x64 CTA tile, 256 thr = 8 warps (4m x 2n), warptile 32x64.
// 3-stage cp.async (2 ahead), ONE sync per 64-k stage. Stride 72 halves.
// MODE 0: A = g_xh, scatter Q(fp16 scaled)/K(fp16)/V(fp16 TRANSPOSED).
// MODE 1: A = g_attnh, C = fp32 out.
// ===========================================================================
#define GBK   64
#define BKPH  72          // padded stride in halves (144B rows, conflict-free)
#define GBM   128
#define GBN   128
#define STG   3
#define GEMM_SMEM ((STG * GBM * BKPH + STG * GBN * BKPH) * 2)   // 110592

template <int MODE>
__global__ __launch_bounds__(256, 2) void gemm_mma(
    const __half* __restrict__ W, const float* __restrict__ bias,
    float* __restrict__ C, int M, int N, int K)
{
    extern __shared__ __half smg[];
    __half* As = smg;                          // [STG][GBM*BKPH]
    __half* Bs = smg + STG * GBM * BKPH;       // [STG][GBN*BKPH]

    const int tid  = threadIdx.x;
    const int lane = tid & 31;
    const int g    = lane >> 2;
    const int t    = lane & 3;
    const int wid  = tid >> 5;
    const int wm   = (wid & 3) * 32;
    const int wn   = (wid >> 2) * 64;
    const int bm   = blockIdx.y;
    const int bn   = blockIdx.x;

    const __half* Ag = (MODE == 1) ? g_attnh : g_xh;

    // staging: thread owns row tid>>1, halves (tid&1)*32 .. +31 (4 cp16)
    const int srow = tid >> 1;
    const int sch  = (tid & 1) * 32;
    const __half* Asrc = Ag + (size_t)(bm * GBM + srow) * K + sch;
    const __half* Bsrc = W  + (size_t)(bn * GBN + srow) * K + sch;

    const uint32_t aDst = smem_u32(As) + (srow * BKPH + sch) * 2;
    const uint32_t bDst = smem_u32(Bs) + (srow * BKPH + sch) * 2;

    float acc[2][8][4];
    #pragma unroll
    for (int mt = 0; mt < 2; mt++)
        #pragma unroll
        for (int nt = 0; nt < 8; nt++)
            #pragma unroll
            for (int e = 0; e < 4; e++) acc[mt][nt][e] = 0.0f;

    const int NS = K / GBK;   // 16

    #pragma unroll
    for (int st = 0; st < 2; st++) {
        const int k0 = st * GBK;
        #pragma unroll
        for (int c = 0; c < 4; c++) {
            cp16(aDst + st * GBM * BKPH * 2 + c * 16, Asrc + k0 + c * 8);
            cp16(bDst + st * GBN * BKPH * 2 + c * 16, Bsrc + k0 + c * 8);
        }
        CP_COMMIT();
    }

    for (int s = 0; s < NS; s++) {
        const int buf = s % STG;
        CP_WAIT(1);            // stage s complete; s+1 in flight
        __syncthreads();       // all warps done reading buf (s-1)%3

        if (s + 2 < NS) {      // refill buf (s+2)%3 == (s-1)%3
            const int nbuf = (s + 2) % STG;
            const int k0 = (s + 2) * GBK;
            #pragma unroll
            for (int c = 0; c < 4; c++) {
                cp16(aDst + nbuf * GBM * BKPH * 2 + c * 16, Asrc + k0 + c * 8);
                cp16(bDst + nbuf * GBN * BKPH * 2 + c * 16, Bsrc + k0 + c * 8);
            }
        }
        CP_COMMIT();

        const __half* Asb = &As[buf * GBM * BKPH];
        const __half* Bsb = &Bs[buf * GBN * BKPH];

        #pragma unroll
        for (int kk = 0; kk < 4; kk++) {        // four k16 chunks
            uint32_t af[2][4];
            #pragma unroll
            for (int mt = 0; mt < 2; mt++) {
                const __half* base = &Asb[(wm + mt * 16) * BKPH + kk * 16 + 2 * t];
                af[mt][0] = lds32(base + g * BKPH);
                af[mt][1] = lds32(base + (g + 8) * BKPH);
                af[mt][2] = lds32(base + g * BKPH + 8);
                af[mt][3] = lds32(base + (g + 8) * BKPH + 8);
            }
            #pragma unroll
            for (int nt = 0; nt < 8; nt++) {
                const __half* bb = &Bsb[(wn + nt * 8 + g) * BKPH + kk * 16 + 2 * t];
                const uint32_t b0 = lds32(bb);
                const uint32_t b1 = lds32(bb + 8);
                #pragma unroll
                for (int mt = 0; mt < 2; mt++)
                    mma_f16(acc[mt][nt], af[mt][0], af[mt][1], af[mt][2], af[mt][3],
                            b0, b1);
            }
        }
    }

    // ---- epilogue ----
    const float QSC = 0.125f * 1.4426950408889634f;
    #pragma unroll
    for (int mt = 0; mt < 2; mt++) {
        #pragma unroll
        for (int half_ = 0; half_ < 2; half_++) {
            const int m = bm * GBM + wm + mt * 16 + g + half_ * 8;
            const int bb_ = m >> 11;
            const int srw = m & 2047;
            #pragma unroll
            for (int nt = 0; nt < 8; nt++) {
                const int n = bn * GBN + wn + nt * 8 + 2 * t;
                float2 bvv = *(const float2*)(bias + n);
                float2 v;
                v.x = acc[mt][nt][half_ * 2 + 0] + bvv.x;
                v.y = acc[mt][nt][half_ * 2 + 1] + bvv.y;
                if (MODE == 0) {
                    const int part = n >> 10;
                    const int hd = n & 1023;
                    const int hh = hd >> 6;
                    const int d = hd & 63;
                    if (part == 0) {
                        const size_t off =
                            (((size_t)(bb_ * NHEADS + hh)) * SEQ + srw) * DHEAD + d;
                        *(__half2*)(g_qh + off) =
                            __floats2half2_rn(v.x * QSC, v.y * QSC);
                    } else if (part == 1) {
                        const size_t off =
                            (((size_t)(bb_ * NHEADS + hh)) * SEQ + srw) * DHEAD + d;
                        *(__half2*)(g_kh + off) = __floats2half2_rn(v.x, v.y);
                    } else {
                        const size_t off =
                            (((size_t)(bb_ * NHEADS + hh)) * DHEAD + d) * SEQ + srw;
                        g_vt[off]       = __float2half_rn(v.x);
                        g_vt[off + SEQ] = __float2half_rn(v.y);
                    }
                } else {
                    *(float2*)(C + (size_t)m * N + n) = v;
                }
            }
        }
    }
}

// ===========================================================================
// Flash attention, FP16 mma.sync m16n8k16, DOUBLE-BUFFERED K/V tiles:
// kv(kt+1) loads while kt computes. 128-row q-tile, 256 thr = 8 warps x 16
// q-rows. Base-2 softmax. Stride 72 halves.
// ===========================================================================
#define FSTRH 72
#define QTILE 128
#define KVT   (64 * FSTRH)       // one K or V buffer (halves)
#define FLASH_SMEM ((2 * KVT + 2 * KVT + QTILE * FSTRH + QTILE * FSTRH) * 2)

__global__ __launch_bounds__(256) void flash_mma(const int* __restrict__ maskFlag)
{
    extern __shared__ __half smf[];
    __half* Ks  = smf;                     // [2][64 keys][FSTRH]
    __half* Vts = Ks + 2 * KVT;            // [2][64 d][FSTRH keys]
    __half* Qs  = Vts + 2 * KVT;           // [128 q][FSTRH]  (persistent)
    __half* Ps  = Qs + QTILE * FSTRH;      // [128 q][FSTRH keys]

    const int tid  = threadIdx.x;
    const int lane = tid & 31;
    const int w    = tid >> 5;
    const int g    = lane >> 2;
    const int t    = lane & 3;
    const int qt   = (int)gridDim.x - 1 - (int)blockIdx.x;
    const int h    = blockIdx.y;
    const int b    = blockIdx.z;
    const int causal = maskFlag[0];

    const size_t bh = (size_t)(b * NHEADS + h) * SEQ * DHEAD;
    const __half* Qg  = g_qh + bh + (size_t)qt * QTILE * DHEAD;
    const __half* Kg  = g_kh + bh;
    const __half* Vtg = g_vt + bh;          // [d][s]

    const uint32_t ksU = smem_u32(Ks);
    const uint32_t vsU = smem_u32(Vts);
    const uint32_t qsU = smem_u32(Qs);

    // staging slices (per thread): 2 cp16 for K, 2 for V per tile
    const int krow = tid >> 3;             // reused below: i>>3 pattern

    // ---- stage Q ----
    #pragma unroll
    for (int j = 0; j < 4; j++) {
        const int i = tid + j * 256;
        const int r  = i >> 3;
        const int c8 = (i & 7) * 8;
        cp16(qsU + (r * FSTRH + c8) * 2, Qg + r * DHEAD + c8);
    }
    CP_COMMIT();

    const int ktEnd = causal ? (2 * qt + 1) : (SEQ / 64 - 1);

    // ---- stage kv(0) into buf 0 ----
    {
        const __half* Kt = Kg;
        const __half* Vk = Vtg;
        #pragma unroll
        for (int j = 0; j < 2; j++) {
            const int i = tid + j * 256;
            const int r  = i >> 3;
            const int c8 = (i & 7) * 8;
            cp16(ksU + (r * FSTRH + c8) * 2, Kt + r * DHEAD + c8);
            cp16(vsU + (r * FSTRH + c8) * 2, Vk + (size_t)r * SEQ + c8);
        }
        CP_COMMIT();
    }
    (void)krow;

    float of[8][4];
    float mA = -CUDART_INF_F, mB = -CUDART_INF_F;
    float lA = 0.0f, lB = 0.0f;
    #pragma unroll
    for (int nt = 0; nt < 8; nt++)
        #pragma unroll
        for (int e = 0; e < 4; e++) of[nt][e] = 0.0f;

    for (int kt = 0; kt <= ktEnd; kt++) {
        const int buf = kt & 1;
        CP_WAIT(0);            // kv(kt) (and Q) arrived
        __syncthreads();       // all warps done reading buf^1 from iter kt-1

        if (kt + 1 <= ktEnd) { // prefetch kv(kt+1) into buf^1
            const uint32_t ko = ksU + (buf ^ 1) * KVT * 2;
            const uint32_t vo = vsU + (buf ^ 1) * KVT * 2;
            const __half* Kt = Kg + (size_t)(kt + 1) * 64 * DHEAD;
            const __half* Vk = Vtg + (size_t)(kt + 1) * 64;
            #pragma unroll
            for (int j = 0; j < 2; j++) {
                const int i = tid + j * 256;
                const int r  = i >> 3;
                const int c8 = (i & 7) * 8;
                cp16(ko + (r * FSTRH + c8) * 2, Kt + r * DHEAD + c8);
                cp16(vo + (r * FSTRH + c8) * 2, Vk + (size_t)r * SEQ + c8);
            }
            CP_COMMIT();
        }

        const __half* Kb = Ks + buf * KVT;
        const __half* Vb = Vts + buf * KVT;

        // ---- S = Q K^T (m16 x n64, k=64: 4 k16 chunks) ----
        float sf[8][4];
        #pragma unroll
        for (int nt = 0; nt < 8; nt++)
            #pragma unroll
            for (int e = 0; e < 4; e++) sf[nt][e] = 0.0f;

        #pragma unroll
        for (int kk = 0; kk < 4; kk++) {
            const __half* qb = &Qs[(w * 16) * FSTRH + kk * 16 + 2 * t];
            const uint32_t a0 = lds32(qb + g * FSTRH);
            const uint32_t a1 = lds32(qb + (g + 8) * FSTRH);
            const uint32_t a2 = lds32(qb + g * FSTRH + 8);
            const uint32_t a3 = lds32(qb + (g + 8) * FSTRH + 8);
            #pragma unroll
            for (int nt = 0; nt < 8; nt++) {
                const __half* kb = &Kb[(nt * 8 + g) * FSTRH + kk * 16 + 2 * t];
                mma_f16(sf[nt], a0, a1, a2, a3, lds32(kb), lds32(kb + 8));
            }
        }

        // ---- causal mask ----
        if (causal && (kt >= 2 * qt)) {
            const int rowb = qt * QTILE + w * 16;
            const int colb = kt * 64;
            #pragma unroll
            for (int nt = 0; nt < 8; nt++) {
                #pragma unroll
                for (int e = 0; e < 4; e++) {
                    const int col = colb + nt * 8 + 2 * t + (e & 1);
                    const int row = rowb + g + ((e >> 1) << 3);
                    if (col > row) sf[nt][e] = -CUDART_INF_F;
                }
            }
        }

        // ---- online softmax in base 2 (rows: A = g, B = g+8) ----
        float mxA = -CUDART_INF_F, mxB = -CUDART_INF_F;
        #pragma unroll
        for (int nt = 0; nt < 8; nt++) {
            mxA = fmaxf(mxA, fmaxf(sf[nt][0], sf[nt][1]));
            mxB = fmaxf(mxB, fmaxf(sf[nt][2], sf[nt][3]));
        }
        mxA = fmaxf(mxA, __shfl_xor_sync(0xffffffffu, mxA, 1));
        mxA = fmaxf(mxA, __shfl_xor_sync(0xffffffffu, mxA, 2));
        mxB = fmaxf(mxB, __shfl_xor_sync(0xffffffffu, mxB, 1));
        mxB = fmaxf(mxB, __shfl_xor_sync(0xffffffffu, mxB, 2));

        const float mnA = fmaxf(mA, mxA);
        const float mnB = fmaxf(mB, mxB);
        const float aA = exp2f(mA - mnA);
        const float aB = exp2f(mB - mnB);
        float sA = 0.0f, sB = 0.0f;
        #pragma unroll
        for (int nt = 0; nt < 8; nt++) {
            sf[nt][0] = exp2f(sf[nt][0] - mnA);
            sf[nt][1] = exp2f(sf[nt][1] - mnA);
            sf[nt][2] = exp2f(sf[nt][2] - mnB);
            sf[nt][3] = exp2f(sf[nt][3] - mnB);
            sA += sf[nt][0] + sf[nt][1];
            sB += sf[nt][2] + sf[nt][3];
        }
        sA += __shfl_xor_sync(0xffffffffu, sA, 1);
        sA += __shfl_xor_sync(0xffffffffu, sA, 2);
        sB += __shfl_xor_sync(0xffffffffu, sB, 1);
        sB += __shfl_xor_sync(0xffffffffu, sB, 2);
        lA = lA * aA + sA;
        lB = lB * aB + sB;
        mA = mnA;
        mB = mnB;
        #pragma unroll
        for (int nt = 0; nt < 8; nt++) {
            of[nt][0] *= aA; of[nt][1] *= aA;
            of[nt][2] *= aB; of[nt][3] *= aB;
        }

        // ---- write P as fp16 pairs (warp-private rows) ----
        #pragma unroll
        for (int nt = 0; nt < 8; nt++) {
            const int c = nt * 8 + 2 * t;
            *(__half2*)&Ps[(w * 16 + g) * FSTRH + c] =
                __floats2half2_rn(sf[nt][0], sf[nt][1]);
            *(__half2*)&Ps[(w * 16 + g + 8) * FSTRH + c] =
                __floats2half2_rn(sf[nt][2], sf[nt][3]);
        }
        __syncwarp();

        // ---- O += P V (m16 x n64, k=64 keys: 4 k16 chunks) ----
        #pragma unroll
        for (int kk = 0; kk < 4; kk++) {
            const __half* pb = &Ps[(w * 16) * FSTRH + kk * 16 + 2 * t];
            const uint32_t a0 = lds32(pb + g * FSTRH);
            const uint32_t a1 = lds32(pb + (g + 8) * FSTRH);
            const uint32_t a2 = lds32(pb + g * FSTRH + 8);
            const uint32_t a3 = lds32(pb + (g + 8) * FSTRH + 8);
            #pragma unroll
            for (int nt = 0; nt < 8; nt++) {
                const __half* vb = &Vb[(nt * 8 + g) * FSTRH + kk * 16 + 2 * t];
                mma_f16(of[nt], a0, a1, a2, a3, lds32(vb), lds32(vb + 8));
            }
        }
    }

    // ---- epilogue: normalize, fp16, store ----
    const float iA = 1.0f / lA;
    const float iB = 1.0f / lB;
    const int qrow = qt * QTILE + w * 16;
    #pragma unroll
    for (int nt = 0; nt < 8; nt++) {
        const int d = h * 64 + nt * 8 + 2 * t;
        *(__half2*)(g_attnh + ((size_t)b * SEQ + qrow + g) * DMODEL + d) =
            __floats2half2_rn(of[nt][0] * iA, of[nt][1] * iA);
        *(__half2*)(g_attnh + ((size_t)b * SEQ + qrow + g + 8) * DMODEL + d) =
            __floats2half2_rn(of[nt][2] * iB, of[nt][3] * iB);
    }
}

// ---------------------------------------------------------------------------
extern "C" void kernel_launch(void* const* d_in, const int* in_sizes, int n_in,
                              void* d_out, int out_size)
{
    const float* x   = (const float*)d_in[0];
    const float* w1  = (const float*)d_in[1];
    const float* b1  = (const float*)d_in[2];
    const float* w2  = (const float*)d_in[3];
    const float* b2  = (const float*)d_in[4];
    const int*   msk = (const int*)  d_in[5];
    float* out = (float*)d_out;

    const int M = BATCH * SEQ;   // 8192

    cudaFuncSetAttribute(gemm_mma<0>,
                         cudaFuncAttributeMaxDynamicSharedMemorySize, GEMM_SMEM);
    cudaFuncSetAttribute(gemm_mma<1>,
                         cudaFuncAttributeMaxDynamicSharedMemorySize, GEMM_SMEM);
    cudaFuncSetAttribute(flash_mma,
                         cudaFuncAttributeMaxDynamicSharedMemorySize, FLASH_SMEM);

    // 0) convert inputs to fp16
    __half* d_xh;  cudaGetSymbolAddress((void**)&d_xh,  g_xh);
    __half* d_w1h; cudaGetSymbolAddress((void**)&d_w1h, g_w1h);
    __half* d_w2h; cudaGetSymbolAddress((void**)&d_w2h, g_w2h);
    {
        const int nx = M * DMODEL / 8;
        to_f16_k<<<(nx + 255) / 256, 256>>>(x, d_xh, nx);
        const int n1 = 3 * DMODEL * DMODEL / 8;
        to_f16_k<<<(n1 + 255) / 256, 256>>>(w1, d_w1h, n1);
        const int n2 = DMODEL * DMODEL / 8;
        to_f16_k<<<(n2 + 255) / 256, 256>>>(w2, d_w2h, n2);
    }

    // 1) QKV projection -> g_qh (scaled) / g_kh / g_vt (transposed)
    gemm_mma<0><<<dim3(3 * DMODEL / GBN, M / GBM), 256, GEMM_SMEM>>>(
        d_w1h, b1, nullptr, M, 3 * DMODEL, DMODEL);

    // 2) Flash attention -> g_attnh
    flash_mma<<<dim3(SEQ / QTILE, NHEADS, BATCH), 256, FLASH_SMEM>>>(msk);

    // 3) Output projection -> d_out (fp32 + bias)
    gemm_mma<1><<<dim3(DMODEL / GBN, M / GBM), 256, GEMM_SMEM>>>(
        d_w2h, b2, out, M, DMODEL, DMODEL);
}

// round 13
// speedup vs baseline: 1.1931x; 1.1931x over previous
#include <cuda_runtime.h>
#include <cuda_fp16.h>
#include <math.h>
#include <math_constants.h>
#include <cstdint>

#define BATCH  4
#define SEQ    2048
#define DMODEL 1024
#define NHEADS 16
#define DHEAD  64

// Scratch (device globals — allocation-free per harness rules)
__device__ __half g_qh[(size_t)BATCH * NHEADS * SEQ * DHEAD];   // [b,h,s,d] scaled
__device__ __half g_kh[(size_t)BATCH * NHEADS * SEQ * DHEAD];   // [b,h,s,d]
__device__ __half g_vt[(size_t)BATCH * NHEADS * DHEAD * SEQ];   // [b,h,d,s]
__device__ __half g_attnh[(size_t)BATCH * SEQ * DMODEL];        // [b,s,dm]
__device__ __half g_xh[(size_t)BATCH * SEQ * DMODEL];
__device__ __half g_w1h[(size_t)3 * DMODEL * DMODEL];
__device__ __half g_w2h[(size_t)DMODEL * DMODEL];

// ---------------------------------------------------------------------------
// helpers
// ---------------------------------------------------------------------------
__device__ __forceinline__ uint32_t smem_u32(const void* p) {
    uint32_t a;
    asm("{ .reg .u64 t; cvta.to.shared.u64 t, %1; cvt.u32.u64 %0, t; }"
        : "=r"(a) : "l"(p));
    return a;
}

__device__ __forceinline__ void cp16(uint32_t dst, const void* src) {
    asm volatile("cp.async.cg.shared.global [%0], [%1], 16;"
                 :: "r"(dst), "l"(src));
}

#define CP_COMMIT()  asm volatile("cp.async.commit_group;" ::: "memory")
#define CP_WAIT(n)   asm volatile("cp.async.wait_group %0;" :: "n"(n) : "memory")

// Warp-collective: load four 8x8 b16 matrices, addrs per-lane.
__device__ __forceinline__ void ldsm4(uint32_t& r0, uint32_t& r1,
                                      uint32_t& r2, uint32_t& r3, uint32_t addr) {
    asm volatile("ldmatrix.sync.aligned.m8n8.x4.shared.b16 {%0,%1,%2,%3}, [%4];"
                 : "=r"(r0), "=r"(r1), "=r"(r2), "=r"(r3) : "r"(addr));
}

// D = A(16x16 f16, row) * B(16x8 f16, col) + D   (f32 accum)
__device__ __forceinline__ void mma_f16(float c[4],
                                        uint32_t a0, uint32_t a1,
                                        uint32_t a2, uint32_t a3,
                                        uint32_t b0, uint32_t b1) {
    asm volatile(
        "mma.sync.aligned.m16n8k16.row.col.f32.f16.f16.f32 "
        "{%0,%1,%2,%3}, {%4,%5,%6,%7}, {%8,%9}, {%0,%1,%2,%3};"
        : "+f"(c[0]), "+f"(c[1]), "+f"(c[2]), "+f"(c[3])
        : "r"(a0), "r"(a1), "r"(a2), "r"(a3), "r"(b0), "r"(b1));
}

// ---------------------------------------------------------------------------
// one-time fp32 -> fp16 conversion
// ---------------------------------------------------------------------------
__global__ __launch_bounds__(256) void to_f16_k(
    const float* __restrict__ s, __half* __restrict__ d, int ngrp)
{
    int i = blockIdx.x * blockDim.x + threadIdx.x;
    if (i < ngrp) {
        float4 v0 = *(const float4*)(s + (size_t)i * 8);
        float4 v1 = *(const float4*)(s + (size_t)i * 8 + 4);
        __half2* o = (__half2*)(d + (size_t)i * 8);
        o[0] = __floats2half2_rn(v0.x, v0.y);
        o[1] = __floats2half2_rn(v0.z, v0.w);
        o[2] = __floats2half2_rn(v1.x, v1.y);
        o[3] = __floats2half2_rn(v1.z, v1.w);
    }
}

// ===========================================================================
// FP16 mma.sync GEMM (NT): C[m,n] = sum_k A[m,k] * W[n,k] + bias[n]
// 128x128x32 CTA tile, 256 thr = 8 warps (4m x 2n), warptile 32x64.
// 4-stage cp.async, one sync per stage. ldmatrix fragment loads.
// MODE 0: scatter Q(fp16 scaled)/K(fp16)/V(fp16 transposed). MODE 1: fp32 C.
// ===========================================================================
#define GBK   32
#define BKPH  40
#define GBM   128
#define GBN   128
#define STG   4
#define GEMM_SMEM ((STG * GBM * BKPH + STG * GBN * BKPH) * 2)   // 81920

template <int MODE>
__global__ __launch_bounds__(256, 2) void gemm_mma(
    const __half* __restrict__ W, const float* __restrict__ bias,
    float* __restrict__ C, int M, int N, int K)
{
    extern __shared__ __half smg[];
    __half* As = smg;                          // [STG][GBM*BKPH]
    __half* Bs = smg + STG * GBM * BKPH;       // [STG][GBN*BKPH]

    const int tid  = threadIdx.x;
    const int lane = tid & 31;
    const int g    = lane >> 2;
    const int t    = lane & 3;
    const int wid  = tid >> 5;
    const int wm   = (wid & 3) * 32;
    const int wn   = (wid >> 2) * 64;
    const int bm   = blockIdx.y;
    const int bn   = blockIdx.x;

    const __half* Ag = (MODE == 1) ? g_attnh : g_xh;

    // staging: thread owns row tid>>1, halves (tid&1)*16 .. +15 (2 cp16)
    const int srow = tid >> 1;
    const int sch  = (tid & 1) * 16;
    const __half* Asrc = Ag + (size_t)(bm * GBM + srow) * K + sch;
    const __half* Bsrc = W  + (size_t)(bn * GBN + srow) * K + sch;

    const uint32_t aDst = smem_u32(As) + (srow * BKPH + sch) * 2;
    const uint32_t bDst = smem_u32(Bs) + (srow * BKPH + sch) * 2;

    // ldmatrix per-lane address components
    const int aRowL = ((lane >> 3) & 1) * 8 + (lane & 7);   // A: x4 m16k16
    const int aKL   = ((lane >> 4) & 1) * 8;
    const int bRowL = ((lane >> 4) & 1) * 8 + (lane & 7);   // B: x4 = two n8k16
    const int bKL   = ((lane >> 3) & 1) * 8;
    const uint32_t aFB = smem_u32(As) + ((wm + aRowL) * BKPH + aKL) * 2;
    const uint32_t bFB = smem_u32(Bs) + ((wn + bRowL) * BKPH + bKL) * 2;

    float acc[2][8][4];
    #pragma unroll
    for (int mt = 0; mt < 2; mt++)
        #pragma unroll
        for (int nt = 0; nt < 8; nt++)
            #pragma unroll
            for (int e = 0; e < 4; e++) acc[mt][nt][e] = 0.0f;

    const int NS = K / GBK;

    #pragma unroll
    for (int st = 0; st < 3; st++) {
        const int k0 = st * GBK;
        cp16(aDst + st * GBM * BKPH * 2,      Asrc + k0);
        cp16(aDst + st * GBM * BKPH * 2 + 16, Asrc + k0 + 8);
        cp16(bDst + st * GBN * BKPH * 2,      Bsrc + k0);
        cp16(bDst + st * GBN * BKPH * 2 + 16, Bsrc + k0 + 8);
        CP_COMMIT();
    }

    for (int s = 0; s < NS; s++) {
        const int buf = s & 3;
        CP_WAIT(2);
        __syncthreads();

        if (s + 3 < NS) {
            const int nbuf = (s + 3) & 3;
            const int k0 = (s + 3) * GBK;
            cp16(aDst + nbuf * GBM * BKPH * 2,      Asrc + k0);
            cp16(aDst + nbuf * GBM * BKPH * 2 + 16, Asrc + k0 + 8);
            cp16(bDst + nbuf * GBN * BKPH * 2,      Bsrc + k0);
            cp16(bDst + nbuf * GBN * BKPH * 2 + 16, Bsrc + k0 + 8);
        }
        CP_COMMIT();

        const uint32_t aOff = aFB + buf * GBM * BKPH * 2;
        const uint32_t bOff = bFB + buf * GBN * BKPH * 2;

        #pragma unroll
        for (int kk = 0; kk < 2; kk++) {
            uint32_t af[2][4];
            #pragma unroll
            for (int mt = 0; mt < 2; mt++)
                ldsm4(af[mt][0], af[mt][1], af[mt][2], af[mt][3],
                      aOff + (mt * 16 * BKPH + kk * 16) * 2);
            uint32_t bf[4][4];
            #pragma unroll
            for (int p = 0; p < 4; p++)
                ldsm4(bf[p][0], bf[p][1], bf[p][2], bf[p][3],
                      bOff + (p * 16 * BKPH + kk * 16) * 2);
            #pragma unroll
            for (int nt = 0; nt < 8; nt++) {
                const uint32_t b0 = bf[nt >> 1][(nt & 1) * 2];
                const uint32_t b1 = bf[nt >> 1][(nt & 1) * 2 + 1];
                #pragma unroll
                for (int mt = 0; mt < 2; mt++)
                    mma_f16(acc[mt][nt], af[mt][0], af[mt][1], af[mt][2], af[mt][3],
                            b0, b1);
            }
        }
    }

    // ---- epilogue ----
    const float QSC = 0.125f * 1.4426950408889634f;
    #pragma unroll
    for (int mt = 0; mt < 2; mt++) {
        #pragma unroll
        for (int half_ = 0; half_ < 2; half_++) {
            const int m = bm * GBM + wm + mt * 16 + g + half_ * 8;
            const int bb_ = m >> 11;
            const int srw = m & 2047;
            #pragma unroll
            for (int nt = 0; nt < 8; nt++) {
                const int n = bn * GBN + wn + nt * 8 + 2 * t;
                float2 bvv = *(const float2*)(bias + n);
                float2 v;
                v.x = acc[mt][nt][half_ * 2 + 0] + bvv.x;
                v.y = acc[mt][nt][half_ * 2 + 1] + bvv.y;
                if (MODE == 0) {
                    const int part = n >> 10;
                    const int hd = n & 1023;
                    const int hh = hd >> 6;
                    const int d = hd & 63;
                    if (part == 0) {
                        const size_t off =
                            (((size_t)(bb_ * NHEADS + hh)) * SEQ + srw) * DHEAD + d;
                        *(__half2*)(g_qh + off) =
                            __floats2half2_rn(v.x * QSC, v.y * QSC);
                    } else if (part == 1) {
                        const size_t off =
                            (((size_t)(bb_ * NHEADS + hh)) * SEQ + srw) * DHEAD + d;
                        *(__half2*)(g_kh + off) = __floats2half2_rn(v.x, v.y);
                    } else {
                        const size_t off =
                            (((size_t)(bb_ * NHEADS + hh)) * DHEAD + d) * SEQ + srw;
                        g_vt[off]       = __float2half_rn(v.x);
                        g_vt[off + SEQ] = __float2half_rn(v.y);
                    }
                } else {
                    *(float2*)(C + (size_t)m * N + n) = v;
                }
            }
        }
    }
}

// ===========================================================================
// Flash attention, FP16 mma.sync m16n8k16 + ldmatrix, double-buffered K/V.
// 128-row q-tile, 256 thr = 8 warps x 16 q-rows. Base-2 softmax. Stride 72.
// ===========================================================================
#define FSTRH 72
#define QTILE 128
#define KVT   (64 * FSTRH)
#define FLASH_SMEM ((2 * KVT + 2 * KVT + QTILE * FSTRH + QTILE * FSTRH) * 2)

__global__ __launch_bounds__(256) void flash_mma(const int* __restrict__ maskFlag)
{
    extern __shared__ __half smf[];
    __half* Ks  = smf;                     // [2][64 keys][FSTRH]
    __half* Vts = Ks + 2 * KVT;            // [2][64 d][FSTRH keys]
    __half* Qs  = Vts + 2 * KVT;           // [128 q][FSTRH]
    __half* Ps  = Qs + QTILE * FSTRH;      // [128 q][FSTRH keys]

    const int tid  = threadIdx.x;
    const int lane = tid & 31;
    const int w    = tid >> 5;
    const int g    = lane >> 2;
    const int t    = lane & 3;
    const int qt   = (int)gridDim.x - 1 - (int)blockIdx.x;
    const int h    = blockIdx.y;
    const int b    = blockIdx.z;
    const int causal = maskFlag[0];

    const size_t bh = (size_t)(b * NHEADS + h) * SEQ * DHEAD;
    const __half* Qg  = g_qh + bh + (size_t)qt * QTILE * DHEAD;
    const __half* Kg  = g_kh + bh;
    const __half* Vtg = g_vt + bh;

    const uint32_t ksU = smem_u32(Ks);
    const uint32_t vsU = smem_u32(Vts);
    const uint32_t qsU = smem_u32(Qs);
    const uint32_t psU = smem_u32(Ps);

    // ldmatrix per-lane address components
    const int aRowL = ((lane >> 3) & 1) * 8 + (lane & 7);
    const int aKL   = ((lane >> 4) & 1) * 8;
    const int bRowL = ((lane >> 4) & 1) * 8 + (lane & 7);
    const int bKL   = ((lane >> 3) & 1) * 8;
    const uint32_t qFB = qsU + ((w * 16 + aRowL) * FSTRH + aKL) * 2;
    const uint32_t pFB = psU + ((w * 16 + aRowL) * FSTRH + aKL) * 2;
    const uint32_t kFB = ksU + (bRowL * FSTRH + bKL) * 2;
    const uint32_t vFB = vsU + (bRowL * FSTRH + bKL) * 2;

    // ---- stage Q ----
    #pragma unroll
    for (int j = 0; j < 4; j++) {
        const int i = tid + j * 256;
        const int r  = i >> 3;
        const int c8 = (i & 7) * 8;
        cp16(qsU + (r * FSTRH + c8) * 2, Qg + r * DHEAD + c8);
    }
    CP_COMMIT();

    const int ktEnd = causal ? (2 * qt + 1) : (SEQ / 64 - 1);

    // ---- stage kv(0) into buf 0 ----
    #pragma unroll
    for (int j = 0; j < 2; j++) {
        const int i = tid + j * 256;
        const int r  = i >> 3;
        const int c8 = (i & 7) * 8;
        cp16(ksU + (r * FSTRH + c8) * 2, Kg + r * DHEAD + c8);
        cp16(vsU + (r * FSTRH + c8) * 2, Vtg + (size_t)r * SEQ + c8);
    }
    CP_COMMIT();

    float of[8][4];
    float mA = -CUDART_INF_F, mB = -CUDART_INF_F;
    float lA = 0.0f, lB = 0.0f;
    #pragma unroll
    for (int nt = 0; nt < 8; nt++)
        #pragma unroll
        for (int e = 0; e < 4; e++) of[nt][e] = 0.0f;

    for (int kt = 0; kt <= ktEnd; kt++) {
        const int buf = kt & 1;
        CP_WAIT(0);            // kv(kt) arrived (Q too on first iter)
        __syncthreads();       // all warps done reading buf^1 from iter kt-1

        if (kt + 1 <= ktEnd) { // prefetch kv(kt+1) into buf^1
            const uint32_t ko = ksU + (buf ^ 1) * KVT * 2;
            const uint32_t vo = vsU + (buf ^ 1) * KVT * 2;
            const __half* Kt = Kg + (size_t)(kt + 1) * 64 * DHEAD;
            const __half* Vk = Vtg + (size_t)(kt + 1) * 64;
            #pragma unroll
            for (int j = 0; j < 2; j++) {
                const int i = tid + j * 256;
                const int r  = i >> 3;
                const int c8 = (i & 7) * 8;
                cp16(ko + (r * FSTRH + c8) * 2, Kt + r * DHEAD + c8);
                cp16(vo + (r * FSTRH + c8) * 2, Vk + (size_t)r * SEQ + c8);
            }
            CP_COMMIT();
        }

        const uint32_t kOff = kFB + buf * KVT * 2;
        const uint32_t vOff = vFB + buf * KVT * 2;

        // ---- S = Q K^T (m16 x n64, k=64: 4 k16 chunks) ----
        float sf[8][4];
        #pragma unroll
        for (int nt = 0; nt < 8; nt++)
            #pragma unroll
            for (int e = 0; e < 4; e++) sf[nt][e] = 0.0f;

        #pragma unroll
        for (int kk = 0; kk < 4; kk++) {
            uint32_t qa[4];
            ldsm4(qa[0], qa[1], qa[2], qa[3], qFB + (kk * 16) * 2);
            uint32_t kf[4][4];
            #pragma unroll
            for (int p = 0; p < 4; p++)
                ldsm4(kf[p][0], kf[p][1], kf[p][2], kf[p][3],
                      kOff + (p * 16 * FSTRH + kk * 16) * 2);
            #pragma unroll
            for (int nt = 0; nt < 8; nt++)
                mma_f16(sf[nt], qa[0], qa[1], qa[2], qa[3],
                        kf[nt >> 1][(nt & 1) * 2], kf[nt >> 1][(nt & 1) * 2 + 1]);
        }

        // ---- causal mask ----
        if (causal && (kt >= 2 * qt)) {
            const int rowb = qt * QTILE + w * 16;
            const int colb = kt * 64;
            #pragma unroll
            for (int nt = 0; nt < 8; nt++) {
                #pragma unroll
                for (int e = 0; e < 4; e++) {
                    const int col = colb + nt * 8 + 2 * t + (e & 1);
                    const int row = rowb + g + ((e >> 1) << 3);
                    if (col > row) sf[nt][e] = -CUDART_INF_F;
                }
            }
        }

        // ---- online softmax in base 2 (rows: A = g, B = g+8) ----
        float mxA = -CUDART_INF_F, mxB = -CUDART_INF_F;
        #pragma unroll
        for (int nt = 0; nt < 8; nt++) {
            mxA = fmaxf(mxA, fmaxf(sf[nt][0], sf[nt][1]));
            mxB = fmaxf(mxB, fmaxf(sf[nt][2], sf[nt][3]));
        }
        mxA = fmaxf(mxA, __shfl_xor_sync(0xffffffffu, mxA, 1));
        mxA = fmaxf(mxA, __shfl_xor_sync(0xffffffffu, mxA, 2));
        mxB = fmaxf(mxB, __shfl_xor_sync(0xffffffffu, mxB, 1));
        mxB = fmaxf(mxB, __shfl_xor_sync(0xffffffffu, mxB, 2));

        const float mnA = fmaxf(mA, mxA);
        const float mnB = fmaxf(mB, mxB);
        const float aA = exp2f(mA - mnA);
        const float aB = exp2f(mB - mnB);
        float sA = 0.0f, sB = 0.0f;
        #pragma unroll
        for (int nt = 0; nt < 8; nt++) {
            sf[nt][0] = exp2f(sf[nt][0] - mnA);
            sf[nt][1] = exp2f(sf[nt][1] - mnA);
            sf[nt][2] = exp2f(sf[nt][2] - mnB);
            sf[nt][3] = exp2f(sf[nt][3] - mnB);
            sA += sf[nt][0] + sf[nt][1];
            sB += sf[nt][2] + sf[nt][3];
        }
        sA += __shfl_xor_sync(0xffffffffu, sA, 1);
        sA += __shfl_xor_sync(0xffffffffu, sA, 2);
        sB += __shfl_xor_sync(0xffffffffu, sB, 1);
        sB += __shfl_xor_sync(0xffffffffu, sB, 2);
        lA = lA * aA + sA;
        lB = lB * aB + sB;
        mA = mnA;
        mB = mnB;
        #pragma unroll
        for (int nt = 0; nt < 8; nt++) {
            of[nt][0] *= aA; of[nt][1] *= aA;
            of[nt][2] *= aB; of[nt][3] *= aB;
        }

        // ---- write P as fp16 pairs (warp-private rows) ----
        #pragma unroll
        for (int nt = 0; nt < 8; nt++) {
            const int c = nt * 8 + 2 * t;
            *(__half2*)&Ps[(w * 16 + g) * FSTRH + c] =
                __floats2half2_rn(sf[nt][0], sf[nt][1]);
            *(__half2*)&Ps[(w * 16 + g + 8) * FSTRH + c] =
                __floats2half2_rn(sf[nt][2], sf[nt][3]);
        }
        __syncwarp();

        // ---- O += P V (m16 x n64, k=64 keys: 4 k16 chunks) ----
        #pragma unroll
        for (int kk = 0; kk < 4; kk++) {
            uint32_t pa[4];
            ldsm4(pa[0], pa[1], pa[2], pa[3], pFB + (kk * 16) * 2);
            uint32_t vf[4][4];
            #pragma unroll
            for (int p = 0; p < 4; p++)
                ldsm4(vf[p][0], vf[p][1], vf[p][2], vf[p][3],
                      vOff + (p * 16 * FSTRH + kk * 16) * 2);
            #pragma unroll
            for (int nt = 0; nt < 8; nt++)
                mma_f16(of[nt], pa[0], pa[1], pa[2], pa[3],
                        vf[nt >> 1][(nt & 1) * 2], vf[nt >> 1][(nt & 1) * 2 + 1]);
        }
    }

    // ---- epilogue: normalize, fp16, store ----
    const float iA = 1.0f / lA;
    const float iB = 1.0f / lB;
    const int qrow = qt * QTILE + w * 16;
    #pragma unroll
    for (int nt = 0; nt < 8; nt++) {
        const int d = h * 64 + nt * 8 + 2 * t;
        *(__half2*)(g_attnh + ((size_t)b * SEQ + qrow + g) * DMODEL + d) =
            __floats2half2_rn(of[nt][0] * iA, of[nt][1] * iA);
        *(__half2*)(g_attnh + ((size_t)b * SEQ + qrow + g + 8) * DMODEL + d) =
            __floats2half2_rn(of[nt][2] * iB, of[nt][3] * iB);
    }
}

// ---------------------------------------------------------------------------
extern "C" void kernel_launch(void* const* d_in, const int* in_sizes, int n_in,
                              void* d_out, int out_size)
{
    const float* x   = (const float*)d_in[0];
    const float* w1  = (const float*)d_in[1];
    const float* b1  = (const float*)d_in[2];
    const float* w2  = (const float*)d_in[3];
    const float* b2  = (const float*)d_in[4];
    const int*   msk = (const int*)  d_in[5];
    float* out = (float*)d_out;

    const int M = BATCH * SEQ;   // 8192

    cudaFuncSetAttribute(gemm_mma<0>,
                         cudaFuncAttributeMaxDynamicSharedMemorySize, GEMM_SMEM);
    cudaFuncSetAttribute(gemm_mma<1>,
                         cudaFuncAttributeMaxDynamicSharedMemorySize, GEMM_SMEM);
    cudaFuncSetAttribute(flash_mma,
                         cudaFuncAttributeMaxDynamicSharedMemorySize, FLASH_SMEM);

    // 0) convert inputs to fp16
    __half* d_xh;  cudaGetSymbolAddress((void**)&d_xh,  g_xh);
    __half* d_w1h; cudaGetSymbolAddress((void**)&d_w1h, g_w1h);
    __half* d_w2h; cudaGetSymbolAddress((void**)&d_w2h, g_w2h);
    {
        const int nx = M * DMODEL / 8;
        to_f16_k<<<(nx + 255) / 256, 256>>>(x, d_xh, nx);
        const int n1 = 3 * DMODEL * DMODEL / 8;
        to_f16_k<<<(n1 + 255) / 256, 256>>>(w1, d_w1h, n1);
        const int n2 = DMODEL * DMODEL / 8;
        to_f16_k<<<(n2 + 255) / 256, 256>>>(w2, d_w2h, n2);
    }

    // 1) QKV projection -> g_qh (scaled) / g_kh / g_vt (transposed)
    gemm_mma<0><<<dim3(3 * DMODEL / GBN, M / GBM), 256, GEMM_SMEM>>>(
        d_w1h, b1, nullptr, M, 3 * DMODEL, DMODEL);

    // 2) Flash attention -> g_attnh
    flash_mma<<<dim3(SEQ / QTILE, NHEADS, BATCH), 256, FLASH_SMEM>>>(msk);

    // 3) Output projection -> d_out (fp32 + bias)
    gemm_mma<1><<<dim3(DMODEL / GBN, M / GBM), 256, GEMM_SMEM>>>(
        d_w2h, b2, out, M, DMODEL, DMODEL);
}

// round 16
// speedup vs baseline: 1.2264x; 1.0279x over previous
#include <cuda_runtime.h>
#include <cuda_fp16.h>
#include <math.h>
#include <math_constants.h>
#include <cstdint>

#define BATCH  4
#define SEQ    2048
#define DMODEL 1024
#define NHEADS 16
#define DHEAD  64

// Scratch (device globals — allocation-free per harness rules)
__device__ __half g_qh[(size_t)BATCH * NHEADS * SEQ * DHEAD];   // [b,h,s,d] scaled
__device__ __half g_kh[(size_t)BATCH * NHEADS * SEQ * DHEAD];   // [b,h,s,d]
__device__ __half g_vt[(size_t)BATCH * NHEADS * DHEAD * SEQ];   // [b,h,d,s]
__device__ __half g_attnh[(size_t)BATCH * SEQ * DMODEL];        // [b,s,dm]
__device__ __half g_xh[(size_t)BATCH * SEQ * DMODEL];
__device__ __half g_w1h[(size_t)3 * DMODEL * DMODEL];
__device__ __half g_w2h[(size_t)DMODEL * DMODEL];

// ---------------------------------------------------------------------------
// helpers
// ---------------------------------------------------------------------------
__device__ __forceinline__ uint32_t smem_u32(const void* p) {
    uint32_t a;
    asm("{ .reg .u64 t; cvta.to.shared.u64 t, %1; cvt.u32.u64 %0, t; }"
        : "=r"(a) : "l"(p));
    return a;
}

__device__ __forceinline__ void cp16(uint32_t dst, const void* src) {
    asm volatile("cp.async.cg.shared.global [%0], [%1], 16;"
                 :: "r"(dst), "l"(src));
}

#define CP_COMMIT()  asm volatile("cp.async.commit_group;" ::: "memory")
#define CP_WAIT(n)   asm volatile("cp.async.wait_group %0;" :: "n"(n) : "memory")

// Warp-collective: load four 8x8 b16 matrices.
__device__ __forceinline__ void ldsm4(uint32_t& r0, uint32_t& r1,
                                      uint32_t& r2, uint32_t& r3, uint32_t addr) {
    asm volatile("ldmatrix.sync.aligned.m8n8.x4.shared.b16 {%0,%1,%2,%3}, [%4];"
                 : "=r"(r0), "=r"(r1), "=r"(r2), "=r"(r3) : "r"(addr));
}

// D = A(16x16 f16, row) * B(16x8 f16, col) + D   (f32 accum)
__device__ __forceinline__ void mma_f16(float c[4],
                                        uint32_t a0, uint32_t a1,
                                        uint32_t a2, uint32_t a3,
                                        uint32_t b0, uint32_t b1) {
    asm volatile(
        "mma.sync.aligned.m16n8k16.row.col.f32.f16.f16.f32 "
        "{%0,%1,%2,%3}, {%4,%5,%6,%7}, {%8,%9}, {%0,%1,%2,%3};"
        : "+f"(c[0]), "+f"(c[1]), "+f"(c[2]), "+f"(c[3])
        : "r"(a0), "r"(a1), "r"(a2), "r"(a3), "r"(b0), "r"(b1));
}

// ---------------------------------------------------------------------------
// one-time fp32 -> fp16 conversion, ALL inputs in one launch
// ---------------------------------------------------------------------------
__global__ __launch_bounds__(256) void to_f16_all(
    const float* __restrict__ x, const float* __restrict__ w1,
    const float* __restrict__ w2, int nx, int n1, int n2)
{
    int j = blockIdx.x * blockDim.x + threadIdx.x;
    const float* s;
    __half* d;
    if (j < nx)              { s = x;  d = g_xh; }
    else if ((j -= nx) < n1) { s = w1; d = g_w1h; }
    else if ((j -= n1) < n2) { s = w2; d = g_w2h; }
    else return;
    float4 v0 = *(const float4*)(s + (size_t)j * 8);
    float4 v1 = *(const float4*)(s + (size_t)j * 8 + 4);
    __half2* o = (__half2*)(d + (size_t)j * 8);
    o[0] = __floats2half2_rn(v0.x, v0.y);
    o[1] = __floats2half2_rn(v0.z, v0.w);
    o[2] = __floats2half2_rn(v1.x, v1.y);
    o[3] = __floats2half2_rn(v1.z, v1.w);
}

// ===========================================================================
// FP16 mma.sync GEMM (NT): C[m,n] = sum_k A[m,k] * W[n,k] + bias[n]
// 128x128x32 CTA tile, 256 thr = 8 warps (4m x 2n), warptile 32x64.
// 5-stage cp.async (4 ahead), one sync per stage. ldmatrix fragment loads.
// MODE 0: scatter Q(fp16 scaled)/K(fp16)/V(fp16 transposed). MODE 1: fp32 C.
// ===========================================================================
#define GBK   32
#define BKPH  40
#define GBM   128
#define GBN   128
#define STG   5
#define GEMM_SMEM ((STG * GBM * BKPH + STG * GBN * BKPH) * 2)   // 102400

template <int MODE>
__global__ __launch_bounds__(256, 2) void gemm_mma(
    const __half* __restrict__ W, const float* __restrict__ bias,
    float* __restrict__ C, int M, int N, int K)
{
    extern __shared__ __half smg[];
    __half* As = smg;                          // [STG][GBM*BKPH]
    __half* Bs = smg + STG * GBM * BKPH;       // [STG][GBN*BKPH]

    const int tid  = threadIdx.x;
    const int lane = tid & 31;
    const int g    = lane >> 2;
    const int t    = lane & 3;
    const int wid  = tid >> 5;
    const int wm   = (wid & 3) * 32;
    const int wn   = (wid >> 2) * 64;
    const int bm   = blockIdx.y;
    const int bn   = blockIdx.x;

    const __half* Ag = (MODE == 1) ? g_attnh : g_xh;

    // staging: thread owns row tid>>1, halves (tid&1)*16 .. +15 (2 cp16)
    const int srow = tid >> 1;
    const int sch  = (tid & 1) * 16;
    const __half* Asrc = Ag + (size_t)(bm * GBM + srow) * K + sch;
    const __half* Bsrc = W  + (size_t)(bn * GBN + srow) * K + sch;

    const uint32_t aDst = smem_u32(As) + (srow * BKPH + sch) * 2;
    const uint32_t bDst = smem_u32(Bs) + (srow * BKPH + sch) * 2;

    // ldmatrix per-lane address components
    const int aRowL = ((lane >> 3) & 1) * 8 + (lane & 7);   // A: x4 m16k16
    const int aKL   = ((lane >> 4) & 1) * 8;
    const int bRowL = ((lane >> 4) & 1) * 8 + (lane & 7);   // B: x4 = two n8k16
    const int bKL   = ((lane >> 3) & 1) * 8;
    const uint32_t aFB = smem_u32(As) + ((wm + aRowL) * BKPH + aKL) * 2;
    const uint32_t bFB = smem_u32(Bs) + ((wn + bRowL) * BKPH + bKL) * 2;

    float acc[2][8][4];
    #pragma unroll
    for (int mt = 0; mt < 2; mt++)
        #pragma unroll
        for (int nt = 0; nt < 8; nt++)
            #pragma unroll
            for (int e = 0; e < 4; e++) acc[mt][nt][e] = 0.0f;

    const int NS = K / GBK;

    #pragma unroll
    for (int st = 0; st < 4; st++) {
        const int k0 = st * GBK;
        cp16(aDst + st * GBM * BKPH * 2,      Asrc + k0);
        cp16(aDst + st * GBM * BKPH * 2 + 16, Asrc + k0 + 8);
        cp16(bDst + st * GBN * BKPH * 2,      Bsrc + k0);
        cp16(bDst + st * GBN * BKPH * 2 + 16, Bsrc + k0 + 8);
        CP_COMMIT();
    }

    for (int s = 0; s < NS; s++) {
        const int buf = s % STG;
        CP_WAIT(3);            // stage s complete; up to 3 newer in flight
        __syncthreads();       // all warps done reading buf (s-1)%5

        if (s + 4 < NS) {      // refill buf (s+4)%5 == (s-1)%5
            const int nbuf = (s + 4) % STG;
            const int k0 = (s + 4) * GBK;
            cp16(aDst + nbuf * GBM * BKPH * 2,      Asrc + k0);
            cp16(aDst + nbuf * GBM * BKPH * 2 + 16, Asrc + k0 + 8);
            cp16(bDst + nbuf * GBN * BKPH * 2,      Bsrc + k0);
            cp16(bDst + nbuf * GBN * BKPH * 2 + 16, Bsrc + k0 + 8);
        }
        CP_COMMIT();           // uniform commit count (empty ok)

        const uint32_t aOff = aFB + buf * GBM * BKPH * 2;
        const uint32_t bOff = bFB + buf * GBN * BKPH * 2;

        #pragma unroll
        for (int kk = 0; kk < 2; kk++) {
            uint32_t af[2][4];
            #pragma unroll
            for (int mt = 0; mt < 2; mt++)
                ldsm4(af[mt][0], af[mt][1], af[mt][2], af[mt][3],
                      aOff + (mt * 16 * BKPH + kk * 16) * 2);
            uint32_t bf[4][4];
            #pragma unroll
            for (int p = 0; p < 4; p++)
                ldsm4(bf[p][0], bf[p][1], bf[p][2], bf[p][3],
                      bOff + (p * 16 * BKPH + kk * 16) * 2);
            #pragma unroll
            for (int nt = 0; nt < 8; nt++) {
                const uint32_t b0 = bf[nt >> 1][(nt & 1) * 2];
                const uint32_t b1 = bf[nt >> 1][(nt & 1) * 2 + 1];
                #pragma unroll
                for (int mt = 0; mt < 2; mt++)
                    mma_f16(acc[mt][nt], af[mt][0], af[mt][1], af[mt][2], af[mt][3],
                            b0, b1);
            }
        }
    }

    // ---- epilogue ----
    const float QSC = 0.125f * 1.4426950408889634f;
    #pragma unroll
    for (int mt = 0; mt < 2; mt++) {
        #pragma unroll
        for (int half_ = 0; half_ < 2; half_++) {
            const int m = bm * GBM + wm + mt * 16 + g + half_ * 8;
            const int bb_ = m >> 11;
            const int srw = m & 2047;
            #pragma unroll
            for (int nt = 0; nt < 8; nt++) {
                const int n = bn * GBN + wn + nt * 8 + 2 * t;
                float2 bvv = *(const float2*)(bias + n);
                float2 v;
                v.x = acc[mt][nt][half_ * 2 + 0] + bvv.x;
                v.y = acc[mt][nt][half_ * 2 + 1] + bvv.y;
                if (MODE == 0) {
                    const int part = n >> 10;
                    const int hd = n & 1023;
                    const int hh = hd >> 6;
                    const int d = hd & 63;
                    if (part == 0) {
                        const size_t off =
                            (((size_t)(bb_ * NHEADS + hh)) * SEQ + srw) * DHEAD + d;
                        *(__half2*)(g_qh + off) =
                            __floats2half2_rn(v.x * QSC, v.y * QSC);
                    } else if (part == 1) {
                        const size_t off =
                            (((size_t)(bb_ * NHEADS + hh)) * SEQ + srw) * DHEAD + d;
                        *(__half2*)(g_kh + off) = __floats2half2_rn(v.x, v.y);
                    } else {
                        const size_t off =
                            (((size_t)(bb_ * NHEADS + hh)) * DHEAD + d) * SEQ + srw;
                        g_vt[off]       = __float2half_rn(v.x);
                        g_vt[off + SEQ] = __float2half_rn(v.y);
                    }
                } else {
                    *(float2*)(C + (size_t)m * N + n) = v;
                }
            }
        }
    }
}

// ===========================================================================
// Flash attention, FP16 mma.sync m16n8k16 + ldmatrix, double-buffered K/V.
// V pre-transposed in gmem ([b,h,d,s]). 128-row q-tile, 256 thr = 8 warps x
// 16 q-rows. Base-2 softmax. Stride 72 halves. Early P-store overlap.
// ===========================================================================
#define FSTRH 72
#define QTILE 128
#define KVT   (64 * FSTRH)
#define FLASH_SMEM ((2 * KVT + 2 * KVT + QTILE * FSTRH + QTILE * FSTRH) * 2)

__global__ __launch_bounds__(256) void flash_mma(const int* __restrict__ maskFlag)
{
    extern __shared__ __half smf[];
    __half* Ks  = smf;                     // [2][64 keys][FSTRH d]
    __half* Vts = Ks + 2 * KVT;            // [2][64 d][FSTRH keys]
    __half* Qs  = Vts + 2 * KVT;           // [128 q][FSTRH d]
    __half* Ps  = Qs + QTILE * FSTRH;      // [128 q][FSTRH keys]

    const int tid  = threadIdx.x;
    const int lane = tid & 31;
    const int w    = tid >> 5;
    const int g    = lane >> 2;
    const int t    = lane & 3;
    const int qt   = (int)gridDim.x - 1 - (int)blockIdx.x;
    const int h    = blockIdx.y;
    const int b    = blockIdx.z;
    const int causal = maskFlag[0];

    const size_t bh = (size_t)(b * NHEADS + h) * SEQ * DHEAD;
    const __half* Qg  = g_qh + bh + (size_t)qt * QTILE * DHEAD;
    const __half* Kg  = g_kh + bh;
    const __half* Vtg = g_vt + bh;

    const uint32_t ksU = smem_u32(Ks);
    const uint32_t vsU = smem_u32(Vts);
    const uint32_t qsU = smem_u32(Qs);
    const uint32_t psU = smem_u32(Ps);

    // ldmatrix per-lane address components
    const int aRowL = ((lane >> 3) & 1) * 8 + (lane & 7);
    const int aKL   = ((lane >> 4) & 1) * 8;
    const int bRowL = ((lane >> 4) & 1) * 8 + (lane & 7);
    const int bKL   = ((lane >> 3) & 1) * 8;
    const uint32_t qFB = qsU + ((w * 16 + aRowL) * FSTRH + aKL) * 2;
    const uint32_t pFB = psU + ((w * 16 + aRowL) * FSTRH + aKL) * 2;
    const uint32_t kFB = ksU + (bRowL * FSTRH + bKL) * 2;
    const uint32_t vFB = vsU + (bRowL * FSTRH + bKL) * 2;

    // ---- stage Q ----
    #pragma unroll
    for (int j = 0; j < 4; j++) {
        const int i = tid + j * 256;
        const int r  = i >> 3;
        const int c8 = (i & 7) * 8;
        cp16(qsU + (r * FSTRH + c8) * 2, Qg + r * DHEAD + c8);
    }
    CP_COMMIT();

    const int ktEnd = causal ? (2 * qt + 1) : (SEQ / 64 - 1);

    // ---- stage kv(0) into buf 0 ----
    #pragma unroll
    for (int j = 0; j < 2; j++) {
        const int i = tid + j * 256;
        const int r  = i >> 3;
        const int c8 = (i & 7) * 8;
        cp16(ksU + (r * FSTRH + c8) * 2, Kg + r * DHEAD + c8);
        cp16(vsU + (r * FSTRH + c8) * 2, Vtg + (size_t)r * SEQ + c8);
    }
    CP_COMMIT();

    float of[8][4];
    float mA = -CUDART_INF_F, mB = -CUDART_INF_F;
    float lA = 0.0f, lB = 0.0f;
    #pragma unroll
    for (int nt = 0; nt < 8; nt++)
        #pragma unroll
        for (int e = 0; e < 4; e++) of[nt][e] = 0.0f;

    for (int kt = 0; kt <= ktEnd; kt++) {
        const int buf = kt & 1;
        CP_WAIT(0);            // kv(kt) arrived (Q too on first iter)
        __syncthreads();       // all warps done reading buf^1 from iter kt-1

        if (kt + 1 <= ktEnd) { // prefetch kv(kt+1) into buf^1
            const uint32_t ko = ksU + (buf ^ 1) * KVT * 2;
            const uint32_t vo = vsU + (buf ^ 1) * KVT * 2;
            const __half* Kt = Kg + (size_t)(kt + 1) * 64 * DHEAD;
            const __half* Vk = Vtg + (size_t)(kt + 1) * 64;
            #pragma unroll
            for (int j = 0; j < 2; j++) {
                const int i = tid + j * 256;
                const int r  = i >> 3;
                const int c8 = (i & 7) * 8;
                cp16(ko + (r * FSTRH + c8) * 2, Kt + r * DHEAD + c8);
                cp16(vo + (r * FSTRH + c8) * 2, Vk + (size_t)r * SEQ + c8);
            }
            CP_COMMIT();
        }

        const uint32_t kOff = kFB + buf * KVT * 2;
        const uint32_t vOff = vFB + buf * KVT * 2;

        // ---- S = Q K^T (m16 x n64, k=64: 4 k16 chunks) ----
        float sf[8][4];
        #pragma unroll
        for (int nt = 0; nt < 8; nt++)
            #pragma unroll
            for (int e = 0; e < 4; e++) sf[nt][e] = 0.0f;

        #pragma unroll
        for (int kk = 0; kk < 4; kk++) {
            uint32_t qa[4];
            ldsm4(qa[0], qa[1], qa[2], qa[3], qFB + (kk * 16) * 2);
            uint32_t kf[4][4];
            #pragma unroll
            for (int p = 0; p < 4; p++)
                ldsm4(kf[p][0], kf[p][1], kf[p][2], kf[p][3],
                      kOff + (p * 16 * FSTRH + kk * 16) * 2);
            #pragma unroll
            for (int nt = 0; nt < 8; nt++)
                mma_f16(sf[nt], qa[0], qa[1], qa[2], qa[3],
                        kf[nt >> 1][(nt & 1) * 2], kf[nt >> 1][(nt & 1) * 2 + 1]);
        }

        // ---- causal mask ----
        if (causal && (kt >= 2 * qt)) {
            const int rowb = qt * QTILE + w * 16;
            const int colb = kt * 64;
            #pragma unroll
            for (int nt = 0; nt < 8; nt++) {
                #pragma unroll
                for (int e = 0; e < 4; e++) {
                    const int col = colb + nt * 8 + 2 * t + (e & 1);
                    const int row = rowb + g + ((e >> 1) << 3);
                    if (col > row) sf[nt][e] = -CUDART_INF_F;
                }
            }
        }

        // ---- online softmax in base 2 (rows: A = g, B = g+8) ----
        float mxA = -CUDART_INF_F, mxB = -CUDART_INF_F;
        #pragma unroll
        for (int nt = 0; nt < 8; nt++) {
            mxA = fmaxf(mxA, fmaxf(sf[nt][0], sf[nt][1]));
            mxB = fmaxf(mxB, fmaxf(sf[nt][2], sf[nt][3]));
        }
        mxA = fmaxf(mxA, __shfl_xor_sync(0xffffffffu, mxA, 1));
        mxA = fmaxf(mxA, __shfl_xor_sync(0xffffffffu, mxA, 2));
        mxB = fmaxf(mxB, __shfl_xor_sync(0xffffffffu, mxB, 1));
        mxB = fmaxf(mxB, __shfl_xor_sync(0xffffffffu, mxB, 2));

        const float mnA = fmaxf(mA, mxA);
        const float mnB = fmaxf(mB, mxB);
        const float aA = exp2f(mA - mnA);
        const float aB = exp2f(mB - mnB);
        float sA = 0.0f, sB = 0.0f;
        #pragma unroll
        for (int nt = 0; nt < 8; nt++) {
            sf[nt][0] = exp2f(sf[nt][0] - mnA);
            sf[nt][1] = exp2f(sf[nt][1] - mnA);
            sf[nt][2] = exp2f(sf[nt][2] - mnB);
            sf[nt][3] = exp2f(sf[nt][3] - mnB);
            sA += sf[nt][0] + sf[nt][1];
            sB += sf[nt][2] + sf[nt][3];
        }

        // ---- write P early (STS in flight while scalar work finishes) ----
        #pragma unroll
        for (int nt = 0; nt < 8; nt++) {
            const int c = nt * 8 + 2 * t;
            *(__half2*)&Ps[(w * 16 + g) * FSTRH + c] =
                __floats2half2_rn(sf[nt][0], sf[nt][1]);
            *(__half2*)&Ps[(w * 16 + g + 8) * FSTRH + c] =
                __floats2half2_rn(sf[nt][2], sf[nt][3]);
        }

        sA += __shfl_xor_sync(0xffffffffu, sA, 1);
        sA += __shfl_xor_sync(0xffffffffu, sA, 2);
        sB += __shfl_xor_sync(0xffffffffu, sB, 1);
        sB += __shfl_xor_sync(0xffffffffu, sB, 2);
        lA = lA * aA + sA;
        lB = lB * aB + sB;
        mA = mnA;
        mB = mnB;
        #pragma unroll
        for (int nt = 0; nt < 8; nt++) {
            of[nt][0] *= aA; of[nt][1] *= aA;
            of[nt][2] *= aB; of[nt][3] *= aB;
        }
        __syncwarp();

        // ---- O += P V (m16 x n64, k=64 keys: 4 k16 chunks) ----
        #pragma unroll
        for (int kk = 0; kk < 4; kk++) {
            uint32_t pa[4];
            ldsm4(pa[0], pa[1], pa[2], pa[3], pFB + (kk * 16) * 2);
            uint32_t vf[4][4];
            #pragma unroll
            for (int p = 0; p < 4; p++)
                ldsm4(vf[p][0], vf[p][1], vf[p][2], vf[p][3],
                      vOff + (p * 16 * FSTRH + kk * 16) * 2);
            #pragma unroll
            for (int nt = 0; nt < 8; nt++)
                mma_f16(of[nt], pa[0], pa[1], pa[2], pa[3],
                        vf[nt >> 1][(nt & 1) * 2], vf[nt >> 1][(nt & 1) * 2 + 1]);
        }
    }

    // ---- epilogue: normalize, fp16, store ----
    const float iA = 1.0f / lA;
    const float iB = 1.0f / lB;
    const int qrow = qt * QTILE + w * 16;
    #pragma unroll
    for (int nt = 0; nt < 8; nt++) {
        const int d = h * 64 + nt * 8 + 2 * t;
        *(__half2*)(g_attnh + ((size_t)b * SEQ + qrow + g) * DMODEL + d) =
            __floats2half2_rn(of[nt][0] * iA, of[nt][1] * iA);
        *(__half2*)(g_attnh + ((size_t)b * SEQ + qrow + g + 8) * DMODEL + d) =
            __floats2half2_rn(of[nt][2] * iB, of[nt][3] * iB);
    }
}

// ---------------------------------------------------------------------------
extern "C" void kernel_launch(void* const* d_in, const int* in_sizes, int n_in,
                              void* d_out, int out_size)
{
    const float* x   = (const float*)d_in[0];
    const float* w1  = (const float*)d_in[1];
    const float* b1  = (const float*)d_in[2];
    const float* w2  = (const float*)d_in[3];
    const float* b2  = (const float*)d_in[4];
    const int*   msk = (const int*)  d_in[5];
    float* out = (float*)d_out;

    const int M = BATCH * SEQ;   // 8192

    cudaFuncSetAttribute(gemm_mma<0>,
                         cudaFuncAttributeMaxDynamicSharedMemorySize, GEMM_SMEM);
    cudaFuncSetAttribute(gemm_mma<1>,
                         cudaFuncAttributeMaxDynamicSharedMemorySize, GEMM_SMEM);
    cudaFuncSetAttribute(flash_mma,
                         cudaFuncAttributeMaxDynamicSharedMemorySize, FLASH_SMEM);

    // device addresses of __device__ globals (host-side symbol addr is WRONG)
    __half* d_w1h; cudaGetSymbolAddress((void**)&d_w1h, g_w1h);
    __half* d_w2h; cudaGetSymbolAddress((void**)&d_w2h, g_w2h);

    // 0) convert all inputs to fp16 in ONE launch
    {
        const int nx = M * DMODEL / 8;
        const int n1 = 3 * DMODEL * DMODEL / 8;
        const int n2 = DMODEL * DMODEL / 8;
        const int total = nx + n1 + n2;
        to_f16_all<<<(total + 255) / 256, 256>>>(x, w1, w2, nx, n1, n2);
    }

    // 1) QKV projection -> g_qh (scaled) / g_kh / g_vt (transposed)
    gemm_mma<0><<<dim3(3 * DMODEL / GBN, M / GBM), 256, GEMM_SMEM>>>(
        d_w1h, b1, nullptr, M, 3 * DMODEL, DMODEL);

    // 2) Flash attention -> g_attnh
    flash_mma<<<dim3(SEQ / QTILE, NHEADS, BATCH), 256, FLASH_SMEM>>>(msk);

    // 3) Output projection -> d_out (fp32 + bias)
    gemm_mma<1><<<dim3(DMODEL / GBN, M / GBM), 256, GEMM_SMEM>>>(
        d_w2h, b2, out, M, DMODEL, DMODEL);
}